// round 5
// baseline (speedup 1.0000x reference)
#include <cuda_runtime.h>
#include <cuda_bf16.h>

// Fused CrossEntropy + (LUT-remapped) BCE loss — SINGLE kernel launch.
//
// Identity: LUT values are exactly {0,1}, so torch-style BCE with -100 log
// clamp reduces to 100 * [b_pred != b_tgt] per sample:
// loss = ( sum_i (lse(pred_i) - pred_i[tgt_i]) + 100 * n_mismatch ) / N
//
// Last-block pattern replaces the separate zero/finalize launches (those two
// 1-thread launches cost ~7.5us of graph-serialized wall time in R4).
// The last block writes the output AND resets the accumulators, so every
// graph replay starts from clean state (deterministic, capture-safe).

__device__ double g_acc = 0.0;           // running sum
__device__ unsigned int g_count = 0u;    // blocks-done counter

__device__ __forceinline__ float row_loss(const float* __restrict__ v, int tgt) {
    // safety clamp: never index v[] out of bounds even on dtype surprise
    tgt = (tgt < 0) ? 0 : ((tgt > 9) ? 9 : tgt);

    // max + argmax (first occurrence on ties, matching jnp.argmax)
    float m = v[0];
    int amax = 0;
#pragma unroll
    for (int j = 1; j < 10; j++) {
        if (v[j] > m) { m = v[j]; amax = j; }
    }

    // logsumexp
    float s = 0.0f;
#pragma unroll
    for (int j = 0; j < 10; j++) {
        s += __expf(v[j] - m);
    }
    const float lse = m + __logf(s);

    const float ce = lse - v[tgt];

    // LUT[c] = 1 iff 2 <= c <= 7
    const int bp = (amax >= 2) & (amax <= 7);
    const int bt = (tgt  >= 2) & (tgt  <= 7);

    return ce + ((bp != bt) ? 100.0f : 0.0f);
}

__global__ void __launch_bounds__(256) loss_kernel(
    const float* __restrict__ pred,
    const int* __restrict__ target,
    float* __restrict__ out,
    int n_rows)
{
    const int i  = blockIdx.x * blockDim.x + threadIdx.x;  // pair index
    const int r0 = 2 * i;

    float local = 0.0f;
    if (r0 + 1 < n_rows) {
        // Pair of rows: 80 bytes at byte offset 80*i -> 16B aligned.
        const float4* __restrict__ p =
            reinterpret_cast<const float4*>(pred + (size_t)i * 20);
        float e[20];
        float4 q0 = p[0];
        float4 q1 = p[1];
        float4 q2 = p[2];
        float4 q3 = p[3];
        float4 q4 = p[4];
        e[0]=q0.x; e[1]=q0.y; e[2]=q0.z; e[3]=q0.w;
        e[4]=q1.x; e[5]=q1.y; e[6]=q1.z; e[7]=q1.w;
        e[8]=q2.x; e[9]=q2.y; e[10]=q2.z; e[11]=q2.w;
        e[12]=q3.x; e[13]=q3.y; e[14]=q3.z; e[15]=q3.w;
        e[16]=q4.x; e[17]=q4.y; e[18]=q4.z; e[19]=q4.w;

        const int2 t2 = *reinterpret_cast<const int2*>(target + (size_t)2 * i);

        local = row_loss(e, t2.x) + row_loss(e + 10, t2.y);
    } else if (r0 < n_rows) {
        // odd tail: single row (float2 loads, 8B aligned)
        const float2* __restrict__ p =
            reinterpret_cast<const float2*>(pred + (size_t)r0 * 10);
        float v[10];
#pragma unroll
        for (int j = 0; j < 5; j++) {
            float2 t = p[j];
            v[2 * j] = t.x;
            v[2 * j + 1] = t.y;
        }
        local = row_loss(v, target[r0]);
    }

    // --- block reduction: warp shuffle -> shared -> one double atomic ---
    __shared__ float warp_sums[8];  // 256 threads = 8 warps

#pragma unroll
    for (int off = 16; off > 0; off >>= 1)
        local += __shfl_down_sync(0xFFFFFFFFu, local, off);

    const int lane = threadIdx.x & 31;
    const int wid  = threadIdx.x >> 5;
    if (lane == 0) warp_sums[wid] = local;
    __syncthreads();

    __shared__ bool is_last;
    if (wid == 0) {
        float blk = (lane < 8) ? warp_sums[lane] : 0.0f;
#pragma unroll
        for (int off = 4; off > 0; off >>= 1)
            blk += __shfl_down_sync(0xFFFFFFFFu, blk, off);
        if (lane == 0) {
            atomicAdd(&g_acc, (double)blk);
            __threadfence();
            const unsigned int done = atomicAdd(&g_count, 1u);
            is_last = (done == gridDim.x - 1u);
        }
    }
    __syncthreads();

    // Last block finalizes: write output, reset state for next replay.
    if (is_last && threadIdx.x == 0) {
        out[0] = (float)(g_acc / (double)n_rows);
        g_acc = 0.0;
        __threadfence();
        g_count = 0u;
    }
}

extern "C" void kernel_launch(void* const* d_in, const int* in_sizes, int n_in,
                              void* d_out, int out_size) {
    const float* pred   = (const float*)d_in[0];
    const int*   target = (const int*)d_in[1];
    float*       out    = (float*)d_out;

    const int n_rows  = in_sizes[1];  // target element count = N
    const int n_pairs = (n_rows + 1) / 2;

    const int threads = 256;
    const int blocks = (n_pairs + threads - 1) / threads;
    loss_kernel<<<blocks, threads>>>(pred, target, out, n_rows);
}

// round 6
// speedup vs baseline: 1.3653x; 1.3653x over previous
#include <cuda_runtime.h>
#include <cuda_bf16.h>

// Fused CrossEntropy + (LUT-remapped) BCE loss — single launch.
//
// loss = ( sum_i (lse(pred_i) - pred_i[tgt_i]) + 100 * n_mismatch ) / N
// where mismatch_i = [ (argmax(pred_i) in [2,7]) != (tgt_i in [2,7]) ].
//
// R6 changes vs R5:
//  - no __threadfence (gpu-scope fence emits CCTL.IVALL = L1 flush per block);
//    ordering done with red.release / atom.acq_rel / ld.acquire instead.
//  - no dynamic array indexing (was forcing v[] into local memory: ~88MB of
//    hidden STL/LDL traffic). v[tgt] fetched via register select chain.
//  - argmax eliminated: b_pred = (m27 > m01) & (m27 >= m89), exact w.r.t.
//    first-occurrence tie semantics.
//  - exp path: one FFMA + MUFU.EX2 per class.

__device__ double g_acc = 0.0;
__device__ unsigned int g_count = 0u;

#define LOG2E 1.4426950408889634f
#define LN2   0.6931471805599453f

__device__ __forceinline__ float row_loss(
    float v0, float v1, float v2, float v3, float v4,
    float v5, float v6, float v7, float v8, float v9, int tgt)
{
    tgt = (tgt < 0) ? 0 : ((tgt > 9) ? 9 : tgt);

    // group maxes (FMNMX)
    const float m01 = fmaxf(v0, v1);
    float m27 = fmaxf(fmaxf(fmaxf(v2, v3), fmaxf(v4, v5)), fmaxf(v6, v7));
    const float m89 = fmaxf(v8, v9);
    const float m = fmaxf(fmaxf(m01, m27), m89);

    // b_pred without argmax (exact under first-occurrence ties:
    // indices 0,1 < 2..7 < 8,9)
    const int bp = (m27 > m01) & (m27 >= m89);
    const int bt = (tgt >= 2) & (tgt <= 7);

    // sum exp2(v*log2e - m*log2e): FFMA + EX2 each
    const float mc = m * LOG2E;
    float s;
    s  = exp2f(fmaf(v0, LOG2E, -mc));
    s += exp2f(fmaf(v1, LOG2E, -mc));
    s += exp2f(fmaf(v2, LOG2E, -mc));
    s += exp2f(fmaf(v3, LOG2E, -mc));
    s += exp2f(fmaf(v4, LOG2E, -mc));
    s += exp2f(fmaf(v5, LOG2E, -mc));
    s += exp2f(fmaf(v6, LOG2E, -mc));
    s += exp2f(fmaf(v7, LOG2E, -mc));
    s += exp2f(fmaf(v8, LOG2E, -mc));
    s += exp2f(fmaf(v9, LOG2E, -mc));

    const float lse = fmaf(__log2f(s), LN2, m);

    // v[tgt] via register select chain (no local memory)
    float vt = v0;
    vt = (tgt == 1) ? v1 : vt;
    vt = (tgt == 2) ? v2 : vt;
    vt = (tgt == 3) ? v3 : vt;
    vt = (tgt == 4) ? v4 : vt;
    vt = (tgt == 5) ? v5 : vt;
    vt = (tgt == 6) ? v6 : vt;
    vt = (tgt == 7) ? v7 : vt;
    vt = (tgt == 8) ? v8 : vt;
    vt = (tgt == 9) ? v9 : vt;

    return (lse - vt) + ((bp != bt) ? 100.0f : 0.0f);
}

__global__ void __launch_bounds__(256) loss_kernel(
    const float* __restrict__ pred,
    const int* __restrict__ target,
    float* __restrict__ out,
    int n_rows)
{
    const int i  = blockIdx.x * blockDim.x + threadIdx.x;  // pair index
    const int r0 = 2 * i;

    float local = 0.0f;
    if (r0 + 1 < n_rows) {
        // Pair of rows: 80 bytes at byte offset 80*i -> 16B aligned.
        const float4* __restrict__ p =
            reinterpret_cast<const float4*>(pred + (size_t)i * 20);
        const float4 q0 = p[0];
        const float4 q1 = p[1];
        const float4 q2 = p[2];
        const float4 q3 = p[3];
        const float4 q4 = p[4];
        const int2 t2 = *reinterpret_cast<const int2*>(target + (size_t)2 * i);

        local = row_loss(q0.x, q0.y, q0.z, q0.w,
                         q1.x, q1.y, q1.z, q1.w,
                         q2.x, q2.y, t2.x)
              + row_loss(q2.z, q2.w,
                         q3.x, q3.y, q3.z, q3.w,
                         q4.x, q4.y, q4.z, q4.w, t2.y);
    } else if (r0 < n_rows) {
        // odd tail: single row (float2 loads, 8B aligned)
        const float2* __restrict__ p =
            reinterpret_cast<const float2*>(pred + (size_t)r0 * 10);
        const float2 a0 = p[0];
        const float2 a1 = p[1];
        const float2 a2 = p[2];
        const float2 a3 = p[3];
        const float2 a4 = p[4];
        local = row_loss(a0.x, a0.y, a1.x, a1.y, a2.x,
                         a2.y, a3.x, a3.y, a4.x, a4.y, target[r0]);
    }

    // --- block reduction: warp shuffle -> shared -> one double red ---
    __shared__ float warp_sums[8];  // 256 threads = 8 warps

#pragma unroll
    for (int off = 16; off > 0; off >>= 1)
        local += __shfl_down_sync(0xFFFFFFFFu, local, off);

    const int lane = threadIdx.x & 31;
    const int wid  = threadIdx.x >> 5;
    if (lane == 0) warp_sums[wid] = local;
    __syncthreads();

    __shared__ bool is_last;
    if (wid == 0) {
        float blk = (lane < 8) ? warp_sums[lane] : 0.0f;
#pragma unroll
        for (int off = 4; off > 0; off >>= 1)
            blk += __shfl_down_sync(0xFFFFFFFFu, blk, off);
        if (lane == 0) {
            const double dblk = (double)blk;
            // accumulate with release semantics (no L1-flushing fence)
            asm volatile("red.release.gpu.global.add.f64 [%0], %1;"
                         :: "l"(&g_acc), "d"(dblk) : "memory");
            unsigned int done;
            unsigned int one = 1u;
            asm volatile("atom.acq_rel.gpu.global.add.u32 %0, [%1], %2;"
                         : "=r"(done) : "l"(&g_count), "r"(one) : "memory");
            is_last = (done == gridDim.x - 1u);
        }
    }
    __syncthreads();

    // Last block finalizes: write output, reset state for next replay.
    if (is_last && threadIdx.x == 0) {
        double acc;
        asm volatile("ld.acquire.gpu.global.f64 %0, [%1];"
                     : "=d"(acc) : "l"(&g_acc) : "memory");
        out[0] = (float)(acc / (double)n_rows);
        g_acc = 0.0;
        g_count = 0u;
    }
}

extern "C" void kernel_launch(void* const* d_in, const int* in_sizes, int n_in,
                              void* d_out, int out_size) {
    const float* pred   = (const float*)d_in[0];
    const int*   target = (const int*)d_in[1];
    float*       out    = (float*)d_out;

    const int n_rows  = in_sizes[1];  // target element count = N
    const int n_pairs = (n_rows + 1) / 2;

    const int threads = 256;
    const int blocks = (n_pairs + threads - 1) / threads;
    loss_kernel<<<blocks, threads>>>(pred, target, out, n_rows);
}